// round 5
// baseline (speedup 1.0000x reference)
#include <cuda_runtime.h>
#include <math.h>

#define NMAX 100000
#define EMAX 3200000
#define F_IN 512
#define HID 16
#define NLAB 64

// ---------------- device scratch (no allocations allowed) ----------------
// NOTE: these symbols are ONLY referenced inside device code. Passing a
// __device__ symbol as a kernel argument from host passes the host shadow
// address, which on GB300 (ATS) silently reads host memory instead of
// crashing — that was the round-2..4 bug.
__device__ float g_norm_src[NMAX];
__device__ float g_norm_dst[NMAX];
__device__ int   g_deg_out[NMAX];
__device__ int   g_deg_in[NMAX];
__device__ int   g_row_start[NMAX];
__device__ int   g_fill[NMAX];
__device__ int   g_bsum[256];
__device__ int   g_boff[256];
__device__ int   g_csr[EMAX];
__device__ int   g_esrc[EMAX];
__device__ int   g_edst[EMAX];
__device__ int   g_fmt;               // 0=int64, 1=int32, 2=float32, 3=float64
__device__ float g_hpre[NMAX * HID];  // (X @ W1) * norm_src
__device__ float g_hmid[NMAX * HID];  // relu(spmm*nd + b1) * norm_src
__device__ float g_h2[NMAX * HID];    // spmm2 * nd

// ---------------- edge dtype probe + normalization ----------------
__global__ void k_detect(const void* __restrict__ src, int ecount, int n) {
    __shared__ int ok64, ok32, okf32, okf64;
    if (threadIdx.x == 0) { ok64 = 1; ok32 = 1; okf32 = 1; okf64 = 1; }
    __syncthreads();
    int nprobe = ecount < 1024 ? ecount : 1024;
    for (int e = threadIdx.x; e < nprobe; e += blockDim.x) {
        long long v64 = ((const long long*)src)[e];
        if (v64 < 0 || v64 >= (long long)n) atomicAnd(&ok64, 0);
        int v32 = ((const int*)src)[e];
        if (v32 < 0 || v32 >= n) atomicAnd(&ok32, 0);
        float f = ((const float*)src)[e];
        if (!(f >= 0.f && f < (float)n && f == floorf(f))) atomicAnd(&okf32, 0);
        double d = ((const double*)src)[e];
        if (!(d >= 0.0 && d < (double)n && d == floor(d))) atomicAnd(&okf64, 0);
    }
    __syncthreads();
    if (threadIdx.x == 0)
        g_fmt = ok64 ? 0 : (ok32 ? 1 : (okf32 ? 2 : (okf64 ? 3 : 1)));
}

__global__ void k_convert(const void* __restrict__ src,
                          const void* __restrict__ dst, int ecount, int n) {
    int e = blockIdx.x * blockDim.x + threadIdx.x;
    if (e >= ecount) return;
    int fmt = g_fmt;
    int s, d;
    if (fmt == 0) {
        s = (int)((const long long*)src)[e];
        d = (int)((const long long*)dst)[e];
    } else if (fmt == 1) {
        s = ((const int*)src)[e];
        d = ((const int*)dst)[e];
    } else if (fmt == 2) {
        s = (int)((const float*)src)[e];
        d = (int)((const float*)dst)[e];
    } else {
        s = (int)((const double*)src)[e];
        d = (int)((const double*)dst)[e];
    }
    s = s < 0 ? 0 : (s >= n ? n - 1 : s);
    d = d < 0 ? 0 : (d >= n ? n - 1 : d);
    g_esrc[e] = s;
    g_edst[e] = d;
}

// ---------------- degree / norm / CSR ----------------
__global__ void k_zero_deg(int n) {
    int i = blockIdx.x * blockDim.x + threadIdx.x;
    if (i < n) { g_deg_out[i] = 0; g_deg_in[i] = 0; }
}

__global__ void k_degree(int ecount) {
    int e = blockIdx.x * blockDim.x + threadIdx.x;
    if (e < ecount) {
        atomicAdd(&g_deg_out[g_esrc[e]], 1);
        atomicAdd(&g_deg_in[g_edst[e]], 1);
    }
}

__global__ void k_norm(int n) {
    int i = blockIdx.x * blockDim.x + threadIdx.x;
    if (i < n) {
        int dout = g_deg_out[i]; if (dout < 1) dout = 1;
        int din  = g_deg_in[i];  if (din  < 1) din  = 1;
        g_norm_src[i] = rsqrtf((float)dout);
        g_norm_dst[i] = rsqrtf((float)din);
    }
}

__global__ void k_scan1(int n) {
    __shared__ int s[1024];
    int tid = threadIdx.x;
    int i = blockIdx.x * 1024 + tid;
    int v = (i < n) ? g_deg_in[i] : 0;
    s[tid] = v;
    __syncthreads();
    for (int off = 1; off < 1024; off <<= 1) {
        int t = (tid >= off) ? s[tid - off] : 0;
        __syncthreads();
        s[tid] += t;
        __syncthreads();
    }
    if (i < n) g_row_start[i] = s[tid] - v;
    if (tid == 1023) g_bsum[blockIdx.x] = s[1023];
}

__global__ void k_scan2(int nblocks) {
    if (threadIdx.x == 0 && blockIdx.x == 0) {
        int acc = 0;
        for (int b = 0; b < nblocks; b++) { g_boff[b] = acc; acc += g_bsum[b]; }
    }
}

__global__ void k_scan3(int n) {
    int i = blockIdx.x * blockDim.x + threadIdx.x;
    if (i < n) {
        int rs = g_row_start[i] + g_boff[i >> 10];
        g_row_start[i] = rs;
        g_fill[i] = rs;
    }
}

__global__ void k_csr_fill(int ecount) {
    int e = blockIdx.x * blockDim.x + threadIdx.x;
    if (e < ecount) {
        int d = g_edst[e];
        int pos = atomicAdd(&g_fill[d], 1);
        g_csr[pos] = g_esrc[e];
    }
}

// ---------------- GEMM1: g_hpre[row] = (X[row] @ W1) * norm_src[row] ----------------
__global__ void k_gemm1(const float* __restrict__ X,
                        const float* __restrict__ W1, int n) {
    __shared__ float sW1[F_IN * HID];  // 32 KB
    int tid = threadIdx.x;
    #pragma unroll
    for (int i = tid; i < (F_IN * HID) / 4; i += 128)
        ((float4*)sW1)[i] = ((const float4*)W1)[i];
    __syncthreads();

    int row = blockIdx.x * 128 + tid;
    if (row >= n) return;

    float acc[HID];
    #pragma unroll
    for (int j = 0; j < HID; j++) acc[j] = 0.f;

    const float* xb = X + (size_t)row * F_IN;
    for (int c = 0; c < F_IN; c += 4) {
        float4 xv = *(const float4*)(xb + c);
        const float* w = &sW1[c * HID];
        #pragma unroll
        for (int j = 0; j < HID; j++) acc[j] += xv.x * w[j];
        #pragma unroll
        for (int j = 0; j < HID; j++) acc[j] += xv.y * w[HID + j];
        #pragma unroll
        for (int j = 0; j < HID; j++) acc[j] += xv.z * w[2 * HID + j];
        #pragma unroll
        for (int j = 0; j < HID; j++) acc[j] += xv.w * w[3 * HID + j];
    }
    float ns = g_norm_src[row];
    float* o = g_hpre + row * HID;
    #pragma unroll
    for (int j = 0; j < HID; j += 4) {
        float4 r = make_float4(acc[j] * ns, acc[j + 1] * ns,
                               acc[j + 2] * ns, acc[j + 3] * ns);
        *(float4*)(o + j) = r;
    }
}

// ---------------- SpMM (gather form, CSR by dst) ----------------
// STAGE 1: g_hmid = relu(spmm(g_hpre)*nd + b1) * ns
// STAGE 2: g_h2   = spmm(g_hmid)*nd
// Scratch tables referenced as device symbols (never passed from host).
template <int STAGE>
__global__ void k_spmm(const float* __restrict__ b1, int n, int ecount) {
    int warp = (blockIdx.x * blockDim.x + threadIdx.x) >> 5;
    if (warp >= n) return;
    const float* __restrict__ in = (STAGE == 1) ? g_hpre : g_hmid;
    float* __restrict__ out      = (STAGE == 1) ? g_hmid : g_h2;

    int lane = threadIdx.x & 31;
    int sub = lane & 3;          // which float4 of the 16-float row
    int grp = lane >> 2;         // edge sub-slot (0..7)
    int v = warp;
    int start = g_row_start[v];
    int end = (v + 1 < n) ? g_row_start[v + 1] : ecount;

    float ax = 0.f, ay = 0.f, az = 0.f, aw = 0.f;
    for (int e = start + grp; e < end; e += 8) {
        int s = __ldg(&g_csr[e]);
        float4 x = *(const float4*)(in + s * HID + sub * 4);
        ax += x.x; ay += x.y; az += x.z; aw += x.w;
    }
    #pragma unroll
    for (int off = 4; off < 32; off <<= 1) {
        ax += __shfl_xor_sync(0xffffffff, ax, off);
        ay += __shfl_xor_sync(0xffffffff, ay, off);
        az += __shfl_xor_sync(0xffffffff, az, off);
        aw += __shfl_xor_sync(0xffffffff, aw, off);
    }
    if (lane < 4) {
        float nd = g_norm_dst[v];
        float4 r;
        if (STAGE == 1) {
            float4 bb = ((const float4*)b1)[lane];
            float ns = g_norm_src[v];
            r.x = fmaxf(ax * nd + bb.x, 0.f) * ns;
            r.y = fmaxf(ay * nd + bb.y, 0.f) * ns;
            r.z = fmaxf(az * nd + bb.z, 0.f) * ns;
            r.w = fmaxf(aw * nd + bb.w, 0.f) * ns;
        } else {
            r.x = ax * nd; r.y = ay * nd; r.z = az * nd; r.w = aw * nd;
        }
        *(float4*)(out + v * HID + lane * 4) = r;
    }
}

// ---------------- GEMM2: out = g_h2 @ W2 + b2 ----------------
__global__ void k_gemm2(const float* __restrict__ W2,
                        const float* __restrict__ b2,
                        float* __restrict__ out, int n) {
    __shared__ float sW2[HID * NLAB];
    __shared__ float sb2[NLAB];
    int tid = threadIdx.x;
    for (int i = tid; i < HID * NLAB; i += blockDim.x) sW2[i] = W2[i];
    if (tid < NLAB) sb2[tid] = b2[tid];
    __syncthreads();

    int g = blockIdx.x * blockDim.x + tid;
    if (g >= n * NLAB) return;
    int row = g >> 6;
    int col = g & 63;
    const float* h = g_h2 + row * HID;
    float4 h0 = *(const float4*)(h);
    float4 h1 = *(const float4*)(h + 4);
    float4 h2 = *(const float4*)(h + 8);
    float4 h3 = *(const float4*)(h + 12);
    float acc = sb2[col];
    acc += h0.x * sW2[0 * NLAB + col];
    acc += h0.y * sW2[1 * NLAB + col];
    acc += h0.z * sW2[2 * NLAB + col];
    acc += h0.w * sW2[3 * NLAB + col];
    acc += h1.x * sW2[4 * NLAB + col];
    acc += h1.y * sW2[5 * NLAB + col];
    acc += h1.z * sW2[6 * NLAB + col];
    acc += h1.w * sW2[7 * NLAB + col];
    acc += h2.x * sW2[8 * NLAB + col];
    acc += h2.y * sW2[9 * NLAB + col];
    acc += h2.z * sW2[10 * NLAB + col];
    acc += h2.w * sW2[11 * NLAB + col];
    acc += h3.x * sW2[12 * NLAB + col];
    acc += h3.y * sW2[13 * NLAB + col];
    acc += h3.z * sW2[14 * NLAB + col];
    acc += h3.w * sW2[15 * NLAB + col];
    out[g] = acc;
}

// ---------------- launch ----------------
extern "C" void kernel_launch(void* const* d_in, const int* in_sizes, int n_in,
                              void* d_out, int out_size) {
    int n = out_size / NLAB;
    if (n > NMAX) n = NMAX;

    // Identify inputs by element-count signature (robust to metadata order).
    int idx_X = -1, idx_W1 = -1, idx_b1 = -1, idx_W2 = -1, idx_b2 = -1;
    int idx_e1 = -1, idx_e2 = -1;
    for (int i = 0; i < n_in; i++) {
        int sz = in_sizes[i];
        if (sz == n * F_IN)            idx_X = i;
        else if (sz == F_IN * HID)     idx_W1 = i;
        else if (sz == HID)            idx_b1 = i;
        else if (sz == HID * NLAB)     idx_W2 = i;
        else if (sz == NLAB)           idx_b2 = i;
        else if (idx_e1 < 0)           idx_e1 = i;
        else                           idx_e2 = i;
    }

    // src/dst by ordering convention:
    //  - insertion order (features first): edges AFTER features -> (src, dst)
    //  - alphabetical: edge_dst < edge_src < features -> (dst, src)
    int idx_src, idx_dst;
    if (idx_e1 > idx_X) { idx_src = idx_e1; idx_dst = idx_e2; }
    else                { idx_dst = idx_e1; idx_src = idx_e2; }

    const float* X   = (const float*)d_in[idx_X];
    const float* W1  = (const float*)d_in[idx_W1];
    const float* b1  = (const float*)d_in[idx_b1];
    const float* W2  = (const float*)d_in[idx_W2];
    const float* b2  = (const float*)d_in[idx_b2];
    const void*  esrc = d_in[idx_src];
    const void*  edst = d_in[idx_dst];

    int ecount = in_sizes[idx_src];
    if (ecount > EMAX) ecount = EMAX;

    int gb256_n = (n + 255) / 256;
    int gb256_e = (ecount + 255) / 256;
    int nblocks_scan = (n + 1023) / 1024;

    k_detect<<<1, 256>>>(esrc, ecount, n);
    k_convert<<<gb256_e, 256>>>(esrc, edst, ecount, n);

    k_zero_deg<<<gb256_n, 256>>>(n);
    k_degree<<<gb256_e, 256>>>(ecount);
    k_norm<<<gb256_n, 256>>>(n);
    k_scan1<<<nblocks_scan, 1024>>>(n);
    k_scan2<<<1, 32>>>(nblocks_scan);
    k_scan3<<<gb256_n, 256>>>(n);
    k_csr_fill<<<gb256_e, 256>>>(ecount);

    k_gemm1<<<(n + 127) / 128, 128>>>(X, W1, n);

    int spmm_blocks = (n * 32 + 255) / 256;
    k_spmm<1><<<spmm_blocks, 256>>>(b1, n, ecount);
    k_spmm<2><<<spmm_blocks, 256>>>(b1, n, ecount);

    k_gemm2<<<(n * NLAB + 255) / 256, 256>>>(W2, b2, (float*)d_out, n);
}

// round 6
// speedup vs baseline: 1.1970x; 1.1970x over previous
#include <cuda_runtime.h>
#include <math.h>

#define NMAX 100000
#define EMAX 3200000
#define F_IN 512
#define HID 16
#define NLAB 64

// ---------------- device scratch (no allocations allowed) ----------------
// These symbols are ONLY referenced inside device code (GB300 ATS silently
// accepts host-shadow addresses — never pass them as kernel args).
__device__ float g_norm_src[NMAX];
__device__ float g_norm_dst[NMAX];
__device__ int   g_deg_out[NMAX];
__device__ int   g_deg_in[NMAX];
__device__ int   g_row_start[NMAX];
__device__ int   g_fill[NMAX];
__device__ int   g_bsum[128];
__device__ int   g_csr[EMAX];
__device__ int   g_esrc[EMAX];
__device__ int   g_edst[EMAX];
__device__ int   g_fmt;               // 0=int64, 1=int32, 2=float32, 3=float64
__device__ float g_hpre[NMAX * HID];  // (X @ W1) * norm_src
__device__ float g_hmid[NMAX * HID];  // relu(spmm*nd + b1) * norm_src
__device__ float g_h2[NMAX * HID];    // spmm2 * nd

// ---------------- f32x2 packed-FMA helpers ----------------
__device__ __forceinline__ unsigned long long pack2(float v) {
    unsigned long long r;
    asm("mov.b64 %0, {%1, %1};" : "=l"(r) : "f"(v));
    return r;
}
__device__ __forceinline__ void fma2(unsigned long long& acc,
                                     unsigned long long a,
                                     unsigned long long b) {
    asm("fma.rn.f32x2 %0, %1, %2, %0;" : "+l"(acc) : "l"(a), "l"(b));
}
__device__ __forceinline__ float2 unpack2(unsigned long long v) {
    float2 r;
    asm("mov.b64 {%0, %1}, %2;" : "=f"(r.x), "=f"(r.y) : "l"(v));
    return r;
}

// ---------------- init: zero degrees + edge-dtype probe ----------------
// Probe accepts an interpretation only if ALL 1024 probed values are
// integral and in [0, n). int64/int32/f32/f64 are mutually distinguishable
// for random indices in [0, 100000).
__global__ void k_init(const void* __restrict__ src, int ecount, int n) {
    int i = blockIdx.x * blockDim.x + threadIdx.x;
    if (i < n) { g_deg_out[i] = 0; g_deg_in[i] = 0; }
    if (blockIdx.x == 0) {
        __shared__ int ok64, ok32, okf32, okf64;
        if (threadIdx.x == 0) { ok64 = 1; ok32 = 1; okf32 = 1; okf64 = 1; }
        __syncthreads();
        int nprobe = ecount < 1024 ? ecount : 1024;
        for (int e = threadIdx.x; e < nprobe; e += blockDim.x) {
            long long v64 = ((const long long*)src)[e];
            if (v64 < 0 || v64 >= (long long)n) atomicAnd(&ok64, 0);
            int v32 = ((const int*)src)[e];
            if (v32 < 0 || v32 >= n) atomicAnd(&ok32, 0);
            float f = ((const float*)src)[e];
            if (!(f >= 0.f && f < (float)n && f == floorf(f))) atomicAnd(&okf32, 0);
            double d = ((const double*)src)[e];
            if (!(d >= 0.0 && d < (double)n && d == floor(d))) atomicAnd(&okf64, 0);
        }
        __syncthreads();
        if (threadIdx.x == 0)
            g_fmt = ok64 ? 0 : (ok32 ? 1 : (okf32 ? 2 : (okf64 ? 3 : 1)));
    }
}

// ---------------- fused convert + degree ----------------
__global__ void k_convdeg(const void* __restrict__ src,
                          const void* __restrict__ dst, int ecount, int n) {
    int e = blockIdx.x * blockDim.x + threadIdx.x;
    if (e >= ecount) return;
    int fmt = g_fmt;
    int s, d;
    if (fmt == 0) {
        s = (int)((const long long*)src)[e];
        d = (int)((const long long*)dst)[e];
    } else if (fmt == 1) {
        s = ((const int*)src)[e];
        d = ((const int*)dst)[e];
    } else if (fmt == 2) {
        s = (int)((const float*)src)[e];
        d = (int)((const float*)dst)[e];
    } else {
        s = (int)((const double*)src)[e];
        d = (int)((const double*)dst)[e];
    }
    s = s < 0 ? 0 : (s >= n ? n - 1 : s);
    d = d < 0 ? 0 : (d >= n ? n - 1 : d);
    g_esrc[e] = s;
    g_edst[e] = d;
    atomicAdd(&g_deg_out[s], 1);
    atomicAdd(&g_deg_in[d], 1);
}

// ---------------- scans (shuffle-based) ----------------
__global__ void k_scan1(int n) {
    __shared__ int wsum[32];
    int tid = threadIdx.x;
    int i = blockIdx.x * 1024 + tid;
    int lane = tid & 31, wid = tid >> 5;
    int v = (i < n) ? g_deg_in[i] : 0;
    int s = v;
    #pragma unroll
    for (int off = 1; off < 32; off <<= 1) {
        int t = __shfl_up_sync(0xffffffff, s, off);
        if (lane >= off) s += t;
    }
    if (lane == 31) wsum[wid] = s;
    __syncthreads();
    if (wid == 0) {
        int w = wsum[lane];
        #pragma unroll
        for (int off = 1; off < 32; off <<= 1) {
            int t = __shfl_up_sync(0xffffffff, w, off);
            if (lane >= off) w += t;
        }
        wsum[lane] = w;
    }
    __syncthreads();
    int base = (wid > 0) ? wsum[wid - 1] : 0;
    int incl = s + base;
    if (i < n) g_row_start[i] = incl - v;   // exclusive within block
    if (tid == 1023) g_bsum[blockIdx.x] = incl;
}

// exclusive scan over <=128 block sums, one block of 128 threads
__global__ void k_scan2(int nblocks) {
    __shared__ int wsum[4];
    int tid = threadIdx.x;
    int lane = tid & 31, wid = tid >> 5;
    int v = (tid < nblocks) ? g_bsum[tid] : 0;
    int s = v;
    #pragma unroll
    for (int off = 1; off < 32; off <<= 1) {
        int t = __shfl_up_sync(0xffffffff, s, off);
        if (lane >= off) s += t;
    }
    if (lane == 31) wsum[wid] = s;
    __syncthreads();
    int base = 0;
    for (int w = 0; w < wid; w++) base += wsum[w];
    if (tid < nblocks) g_bsum[tid] = s + base - v;  // exclusive
}

// row_start finalize + fill init + norms (fused)
__global__ void k_scan3(int n) {
    int i = blockIdx.x * blockDim.x + threadIdx.x;
    if (i >= n) return;
    int rs = g_row_start[i] + g_bsum[i >> 10];
    g_row_start[i] = rs;
    g_fill[i] = rs;
    int dout = g_deg_out[i]; if (dout < 1) dout = 1;
    int din  = g_deg_in[i];  if (din  < 1) din  = 1;
    g_norm_src[i] = rsqrtf((float)dout);
    g_norm_dst[i] = rsqrtf((float)din);
}

__global__ void k_csr_fill(int ecount) {
    int e = blockIdx.x * blockDim.x + threadIdx.x;
    if (e < ecount) {
        int d = g_edst[e];
        int pos = atomicAdd(&g_fill[d], 1);
        g_csr[pos] = g_esrc[e];
    }
}

// ---------------- GEMM1: g_hpre[row] = (X[row] @ W1) * norm_src[row] ----------------
// 2 rows/thread, packed f32x2 FMA (FFMA2), W1 broadcast from shared.
__global__ void k_gemm1(const float* __restrict__ X,
                        const float* __restrict__ W1, int n) {
    __shared__ float sW1[F_IN * HID];  // 32 KB
    int tid = threadIdx.x;             // 256 threads
    #pragma unroll
    for (int i = tid; i < (F_IN * HID) / 4; i += 256)
        ((float4*)sW1)[i] = ((const float4*)W1)[i];
    __syncthreads();

    int row0 = blockIdx.x * 512 + tid;
    int row1 = row0 + 256;
    if (row0 >= n) return;
    bool has1 = (row1 < n);
    int row1c = has1 ? row1 : row0;

    unsigned long long acc0[8], acc1[8];
    #pragma unroll
    for (int p = 0; p < 8; p++) { acc0[p] = 0ull; acc1[p] = 0ull; }

    const float* xb0 = X + (size_t)row0 * F_IN;
    const float* xb1 = X + (size_t)row1c * F_IN;

    for (int c = 0; c < F_IN; c += 4) {
        float4 x0 = *(const float4*)(xb0 + c);
        float4 x1 = *(const float4*)(xb1 + c);
        const float xs0[4] = {x0.x, x0.y, x0.z, x0.w};
        const float xs1[4] = {x1.x, x1.y, x1.z, x1.w};
        #pragma unroll
        for (int k = 0; k < 4; k++) {
            unsigned long long xp0 = pack2(xs0[k]);
            unsigned long long xp1 = pack2(xs1[k]);
            const unsigned long long* w =
                (const unsigned long long*)&sW1[(c + k) * HID];
            #pragma unroll
            for (int p = 0; p < 8; p++) {
                unsigned long long wp = w[p];
                fma2(acc0[p], xp0, wp);
                fma2(acc1[p], xp1, wp);
            }
        }
    }

    float ns0 = g_norm_src[row0];
    float* o0 = g_hpre + row0 * HID;
    #pragma unroll
    for (int p = 0; p < 8; p += 2) {
        float2 a = unpack2(acc0[p]);
        float2 b = unpack2(acc0[p + 1]);
        *(float4*)(o0 + 2 * p) =
            make_float4(a.x * ns0, a.y * ns0, b.x * ns0, b.y * ns0);
    }
    if (has1) {
        float ns1 = g_norm_src[row1];
        float* o1 = g_hpre + row1 * HID;
        #pragma unroll
        for (int p = 0; p < 8; p += 2) {
            float2 a = unpack2(acc1[p]);
            float2 b = unpack2(acc1[p + 1]);
            *(float4*)(o1 + 2 * p) =
                make_float4(a.x * ns1, a.y * ns1, b.x * ns1, b.y * ns1);
        }
    }
}

// ---------------- SpMM (gather form, CSR by dst) ----------------
// STAGE 1: g_hmid = relu(spmm(g_hpre)*nd + b1) * ns
// STAGE 2: g_h2   = spmm(g_hmid)*nd
template <int STAGE>
__global__ void k_spmm(const float* __restrict__ b1, int n, int ecount) {
    int warp = (blockIdx.x * blockDim.x + threadIdx.x) >> 5;
    if (warp >= n) return;
    const float* __restrict__ in = (STAGE == 1) ? g_hpre : g_hmid;
    float* __restrict__ out      = (STAGE == 1) ? g_hmid : g_h2;

    int lane = threadIdx.x & 31;
    int sub = lane & 3;          // which float4 of the 16-float row
    int grp = lane >> 2;         // edge sub-slot (0..7)
    int v = warp;
    int start = g_row_start[v];
    int end = (v + 1 < n) ? g_row_start[v + 1] : ecount;

    float ax = 0.f, ay = 0.f, az = 0.f, aw = 0.f;
    for (int e = start + grp; e < end; e += 8) {
        int s = __ldg(&g_csr[e]);
        float4 x = *(const float4*)(in + s * HID + sub * 4);
        ax += x.x; ay += x.y; az += x.z; aw += x.w;
    }
    #pragma unroll
    for (int off = 4; off < 32; off <<= 1) {
        ax += __shfl_xor_sync(0xffffffff, ax, off);
        ay += __shfl_xor_sync(0xffffffff, ay, off);
        az += __shfl_xor_sync(0xffffffff, az, off);
        aw += __shfl_xor_sync(0xffffffff, aw, off);
    }
    if (lane < 4) {
        float nd = g_norm_dst[v];
        float4 r;
        if (STAGE == 1) {
            float4 bb = ((const float4*)b1)[lane];
            float ns = g_norm_src[v];
            r.x = fmaxf(ax * nd + bb.x, 0.f) * ns;
            r.y = fmaxf(ay * nd + bb.y, 0.f) * ns;
            r.z = fmaxf(az * nd + bb.z, 0.f) * ns;
            r.w = fmaxf(aw * nd + bb.w, 0.f) * ns;
        } else {
            r.x = ax * nd; r.y = ay * nd; r.z = az * nd; r.w = aw * nd;
        }
        *(float4*)(out + v * HID + lane * 4) = r;
    }
}

// ---------------- GEMM2: out = g_h2 @ W2 + b2 ----------------
__global__ void k_gemm2(const float* __restrict__ W2,
                        const float* __restrict__ b2,
                        float* __restrict__ out, int n) {
    __shared__ float sW2[HID * NLAB];
    __shared__ float sb2[NLAB];
    int tid = threadIdx.x;
    for (int i = tid; i < HID * NLAB; i += blockDim.x) sW2[i] = W2[i];
    if (tid < NLAB) sb2[tid] = b2[tid];
    __syncthreads();

    int g = blockIdx.x * blockDim.x + tid;
    if (g >= n * NLAB) return;
    int row = g >> 6;
    int col = g & 63;
    const float* h = g_h2 + row * HID;
    float4 h0 = *(const float4*)(h);
    float4 h1 = *(const float4*)(h + 4);
    float4 h2 = *(const float4*)(h + 8);
    float4 h3 = *(const float4*)(h + 12);
    float acc = sb2[col];
    acc += h0.x * sW2[0 * NLAB + col];
    acc += h0.y * sW2[1 * NLAB + col];
    acc += h0.z * sW2[2 * NLAB + col];
    acc += h0.w * sW2[3 * NLAB + col];
    acc += h1.x * sW2[4 * NLAB + col];
    acc += h1.y * sW2[5 * NLAB + col];
    acc += h1.z * sW2[6 * NLAB + col];
    acc += h1.w * sW2[7 * NLAB + col];
    acc += h2.x * sW2[8 * NLAB + col];
    acc += h2.y * sW2[9 * NLAB + col];
    acc += h2.z * sW2[10 * NLAB + col];
    acc += h2.w * sW2[11 * NLAB + col];
    acc += h3.x * sW2[12 * NLAB + col];
    acc += h3.y * sW2[13 * NLAB + col];
    acc += h3.z * sW2[14 * NLAB + col];
    acc += h3.w * sW2[15 * NLAB + col];
    out[g] = acc;
}

// ---------------- launch ----------------
extern "C" void kernel_launch(void* const* d_in, const int* in_sizes, int n_in,
                              void* d_out, int out_size) {
    int n = out_size / NLAB;
    if (n > NMAX) n = NMAX;

    // Identify inputs by element-count signature (robust to metadata order).
    int idx_X = -1, idx_W1 = -1, idx_b1 = -1, idx_W2 = -1, idx_b2 = -1;
    int idx_e1 = -1, idx_e2 = -1;
    for (int i = 0; i < n_in; i++) {
        int sz = in_sizes[i];
        if (sz == n * F_IN)            idx_X = i;
        else if (sz == F_IN * HID)     idx_W1 = i;
        else if (sz == HID)            idx_b1 = i;
        else if (sz == HID * NLAB)     idx_W2 = i;
        else if (sz == NLAB)           idx_b2 = i;
        else if (idx_e1 < 0)           idx_e1 = i;
        else                           idx_e2 = i;
    }

    // src/dst by ordering convention (see round-3 notes).
    int idx_src, idx_dst;
    if (idx_e1 > idx_X) { idx_src = idx_e1; idx_dst = idx_e2; }
    else                { idx_dst = idx_e1; idx_src = idx_e2; }

    const float* X   = (const float*)d_in[idx_X];
    const float* W1  = (const float*)d_in[idx_W1];
    const float* b1  = (const float*)d_in[idx_b1];
    const float* W2  = (const float*)d_in[idx_W2];
    const float* b2  = (const float*)d_in[idx_b2];
    const void*  esrc = d_in[idx_src];
    const void*  edst = d_in[idx_dst];

    int ecount = in_sizes[idx_src];
    if (ecount > EMAX) ecount = EMAX;

    int gb256_n = (n + 255) / 256;
    int gb256_e = (ecount + 255) / 256;
    int nblocks_scan = (n + 1023) / 1024;

    k_init<<<gb256_n, 256>>>(esrc, ecount, n);
    k_convdeg<<<gb256_e, 256>>>(esrc, edst, ecount, n);
    k_scan1<<<nblocks_scan, 1024>>>(n);
    k_scan2<<<1, 128>>>(nblocks_scan);
    k_scan3<<<gb256_n, 256>>>(n);
    k_csr_fill<<<gb256_e, 256>>>(ecount);

    k_gemm1<<<(n + 511) / 512, 256>>>(X, W1, n);

    int spmm_blocks = (n * 32 + 255) / 256;
    k_spmm<1><<<spmm_blocks, 256>>>(b1, n, ecount);
    k_spmm<2><<<spmm_blocks, 256>>>(b1, n, ecount);

    k_gemm2<<<(n * NLAB + 255) / 256, 256>>>(W2, b2, (float*)d_out, n);
}

// round 7
// speedup vs baseline: 1.2922x; 1.0795x over previous
#include <cuda_runtime.h>
#include <math.h>

#define NMAX 100000
#define EMAX 3200000
#define F_IN 512
#define HID 16
#define NLAB 64

// ---------------- device scratch (no allocations allowed) ----------------
// These symbols are ONLY referenced inside device code (GB300 ATS silently
// accepts host-shadow addresses — never pass them as kernel args).
__device__ float g_norm_src[NMAX];
__device__ float g_norm_dst[NMAX];
__device__ int   g_deg_out[NMAX];
__device__ int   g_deg_in[NMAX];
__device__ int   g_row_start[NMAX];
__device__ int   g_fill[NMAX];
__device__ int   g_bsum[128];
__device__ int   g_csr[EMAX];
__device__ int   g_esrc[EMAX];
__device__ int   g_edst[EMAX];
__device__ int   g_fmt;               // 0=int64, 1=int32, 2=float32, 3=float64
__device__ float g_hpre[NMAX * HID];  // (X @ W1) * norm_src
__device__ float g_hmid[NMAX * HID];  // relu(spmm*nd + b1) * norm_src

// ---------------- f32x2 packed-FMA helpers ----------------
__device__ __forceinline__ unsigned long long pack2(float v) {
    unsigned long long r;
    asm("mov.b64 %0, {%1, %1};" : "=l"(r) : "f"(v));
    return r;
}
__device__ __forceinline__ void fma2(unsigned long long& acc,
                                     unsigned long long a,
                                     unsigned long long b) {
    asm("fma.rn.f32x2 %0, %1, %2, %0;" : "+l"(acc) : "l"(a), "l"(b));
}
__device__ __forceinline__ float2 unpack2(unsigned long long v) {
    float2 r;
    asm("mov.b64 {%0, %1}, %2;" : "=f"(r.x), "=f"(r.y) : "l"(v));
    return r;
}

// ---------------- init: zero degrees + edge-dtype probe ----------------
__global__ void k_init(const void* __restrict__ src, int ecount, int n) {
    int i = blockIdx.x * blockDim.x + threadIdx.x;
    if (i < n) { g_deg_out[i] = 0; g_deg_in[i] = 0; }
    if (blockIdx.x == 0) {
        __shared__ int ok64, ok32, okf32, okf64;
        if (threadIdx.x == 0) { ok64 = 1; ok32 = 1; okf32 = 1; okf64 = 1; }
        __syncthreads();
        int nprobe = ecount < 1024 ? ecount : 1024;
        for (int e = threadIdx.x; e < nprobe; e += blockDim.x) {
            long long v64 = ((const long long*)src)[e];
            if (v64 < 0 || v64 >= (long long)n) atomicAnd(&ok64, 0);
            int v32 = ((const int*)src)[e];
            if (v32 < 0 || v32 >= n) atomicAnd(&ok32, 0);
            float f = ((const float*)src)[e];
            if (!(f >= 0.f && f < (float)n && f == floorf(f))) atomicAnd(&okf32, 0);
            double d = ((const double*)src)[e];
            if (!(d >= 0.0 && d < (double)n && d == floor(d))) atomicAnd(&okf64, 0);
        }
        __syncthreads();
        if (threadIdx.x == 0)
            g_fmt = ok64 ? 0 : (ok32 ? 1 : (okf32 ? 2 : (okf64 ? 3 : 1)));
    }
}

// ---------------- fused convert + degree (streaming reads) ----------------
__global__ void k_convdeg(const void* __restrict__ src,
                          const void* __restrict__ dst, int ecount, int n) {
    int e = blockIdx.x * blockDim.x + threadIdx.x;
    if (e >= ecount) return;
    int fmt = g_fmt;
    int s, d;
    if (fmt == 0) {
        s = (int)__ldcs((const long long*)src + e);
        d = (int)__ldcs((const long long*)dst + e);
    } else if (fmt == 1) {
        s = __ldcs((const int*)src + e);
        d = __ldcs((const int*)dst + e);
    } else if (fmt == 2) {
        s = (int)__ldcs((const float*)src + e);
        d = (int)__ldcs((const float*)dst + e);
    } else {
        s = (int)__ldcs((const double*)src + e);
        d = (int)__ldcs((const double*)dst + e);
    }
    s = s < 0 ? 0 : (s >= n ? n - 1 : s);
    d = d < 0 ? 0 : (d >= n ? n - 1 : d);
    g_esrc[e] = s;
    g_edst[e] = d;
    atomicAdd(&g_deg_out[s], 1);
    atomicAdd(&g_deg_in[d], 1);
}

// ---------------- scan over deg_in (block-level, shuffle) ----------------
__global__ void k_scan1(int n) {
    __shared__ int wsum[32];
    int tid = threadIdx.x;
    int i = blockIdx.x * 1024 + tid;
    int lane = tid & 31, wid = tid >> 5;
    int v = (i < n) ? g_deg_in[i] : 0;
    int s = v;
    #pragma unroll
    for (int off = 1; off < 32; off <<= 1) {
        int t = __shfl_up_sync(0xffffffff, s, off);
        if (lane >= off) s += t;
    }
    if (lane == 31) wsum[wid] = s;
    __syncthreads();
    if (wid == 0) {
        int w = wsum[lane];
        #pragma unroll
        for (int off = 1; off < 32; off <<= 1) {
            int t = __shfl_up_sync(0xffffffff, w, off);
            if (lane >= off) w += t;
        }
        wsum[lane] = w;
    }
    __syncthreads();
    int base = (wid > 0) ? wsum[wid - 1] : 0;
    int incl = s + base;
    if (i < n) g_row_start[i] = incl - v;   // exclusive within block
    if (tid == 1023) g_bsum[blockIdx.x] = incl;
}

// finalize row_start (self-computed bsum prefix) + fill init + norms.
// block = 256 threads; all i in a block share (i>>10) since 256 | 1024.
__global__ void k_scan3(int n) {
    __shared__ int base_s;
    int nb1 = blockIdx.x >> 2;   // this block's scan1-block index
    if (threadIdx.x < 32) {
        int lane = threadIdx.x;
        int acc = 0;
        for (int b = lane; b < nb1; b += 32) acc += g_bsum[b];
        #pragma unroll
        for (int off = 16; off; off >>= 1)
            acc += __shfl_xor_sync(0xffffffff, acc, off);
        if (lane == 0) base_s = acc;
    }
    __syncthreads();
    int i = blockIdx.x * 256 + threadIdx.x;
    if (i >= n) return;
    int rs = g_row_start[i] + base_s;
    g_row_start[i] = rs;
    g_fill[i] = rs;
    int dout = g_deg_out[i]; if (dout < 1) dout = 1;
    int din  = g_deg_in[i];  if (din  < 1) din  = 1;
    g_norm_src[i] = rsqrtf((float)dout);
    g_norm_dst[i] = rsqrtf((float)din);
}

__global__ void k_csr_fill(int ecount) {
    int e = blockIdx.x * blockDim.x + threadIdx.x;
    if (e < ecount) {
        int d = __ldcs(&g_edst[e]);
        int s = __ldcs(&g_esrc[e]);
        int pos = atomicAdd(&g_fill[d], 1);
        g_csr[pos] = s;
    }
}

// ---------------- GEMM1: g_hpre[row] = (X[row] @ W1) * norm_src[row] ----------------
// 2 rows/thread, packed f32x2 FMA; X read with streaming hint (one-shot 205MB).
__global__ void k_gemm1(const float* __restrict__ X,
                        const float* __restrict__ W1, int n) {
    __shared__ float sW1[F_IN * HID];  // 32 KB
    int tid = threadIdx.x;             // 256 threads
    #pragma unroll
    for (int i = tid; i < (F_IN * HID) / 4; i += 256)
        ((float4*)sW1)[i] = ((const float4*)W1)[i];
    __syncthreads();

    int row0 = blockIdx.x * 512 + tid;
    int row1 = row0 + 256;
    if (row0 >= n) return;
    bool has1 = (row1 < n);
    int row1c = has1 ? row1 : row0;

    unsigned long long acc0[8], acc1[8];
    #pragma unroll
    for (int p = 0; p < 8; p++) { acc0[p] = 0ull; acc1[p] = 0ull; }

    const float4* xb0 = (const float4*)(X + (size_t)row0 * F_IN);
    const float4* xb1 = (const float4*)(X + (size_t)row1c * F_IN);

    for (int c = 0; c < F_IN / 4; c++) {
        float4 x0 = __ldcs(xb0 + c);
        float4 x1 = __ldcs(xb1 + c);
        const float xs0[4] = {x0.x, x0.y, x0.z, x0.w};
        const float xs1[4] = {x1.x, x1.y, x1.z, x1.w};
        #pragma unroll
        for (int k = 0; k < 4; k++) {
            unsigned long long xp0 = pack2(xs0[k]);
            unsigned long long xp1 = pack2(xs1[k]);
            const unsigned long long* w =
                (const unsigned long long*)&sW1[(4 * c + k) * HID];
            #pragma unroll
            for (int p = 0; p < 8; p++) {
                unsigned long long wp = w[p];
                fma2(acc0[p], xp0, wp);
                fma2(acc1[p], xp1, wp);
            }
        }
    }

    float ns0 = g_norm_src[row0];
    float* o0 = g_hpre + row0 * HID;
    #pragma unroll
    for (int p = 0; p < 8; p += 2) {
        float2 a = unpack2(acc0[p]);
        float2 b = unpack2(acc0[p + 1]);
        *(float4*)(o0 + 2 * p) =
            make_float4(a.x * ns0, a.y * ns0, b.x * ns0, b.y * ns0);
    }
    if (has1) {
        float ns1 = g_norm_src[row1];
        float* o1 = g_hpre + row1 * HID;
        #pragma unroll
        for (int p = 0; p < 8; p += 2) {
            float2 a = unpack2(acc1[p]);
            float2 b = unpack2(acc1[p + 1]);
            *(float4*)(o1 + 2 * p) =
                make_float4(a.x * ns1, a.y * ns1, b.x * ns1, b.y * ns1);
        }
    }
}

// ---------------- SpMM stage 1: g_hmid = relu(spmm(g_hpre)*nd + b1)*ns ----------------
__global__ void k_spmm1(const float* __restrict__ b1, int n, int ecount) {
    int warp = (blockIdx.x * blockDim.x + threadIdx.x) >> 5;
    if (warp >= n) return;
    int lane = threadIdx.x & 31;
    int sub = lane & 3;
    int grp = lane >> 2;
    int v = warp;
    int start = g_row_start[v];
    int end = (v + 1 < n) ? g_row_start[v + 1] : ecount;

    float ax = 0.f, ay = 0.f, az = 0.f, aw = 0.f;
    for (int e = start + grp; e < end; e += 8) {
        int s = __ldg(&g_csr[e]);
        float4 x = *(const float4*)(g_hpre + s * HID + sub * 4);
        ax += x.x; ay += x.y; az += x.z; aw += x.w;
    }
    #pragma unroll
    for (int off = 4; off < 32; off <<= 1) {
        ax += __shfl_xor_sync(0xffffffff, ax, off);
        ay += __shfl_xor_sync(0xffffffff, ay, off);
        az += __shfl_xor_sync(0xffffffff, az, off);
        aw += __shfl_xor_sync(0xffffffff, aw, off);
    }
    if (lane < 4) {
        float nd = g_norm_dst[v];
        float ns = g_norm_src[v];
        float4 bb = ((const float4*)b1)[lane];
        float4 r;
        r.x = fmaxf(ax * nd + bb.x, 0.f) * ns;
        r.y = fmaxf(ay * nd + bb.y, 0.f) * ns;
        r.z = fmaxf(az * nd + bb.z, 0.f) * ns;
        r.w = fmaxf(aw * nd + bb.w, 0.f) * ns;
        *(float4*)(g_hmid + v * HID + lane * 4) = r;
    }
}

// ---------------- SpMM stage 2 + GEMM2 fused ----------------
// h2[v] = spmm(g_hmid)[v] * nd;  out[v, :] = h2[v] @ W2 + b2
// Warp per node: gather+reduce as stage 1, then broadcast the 16 h2 values
// to all lanes via shuffles; each lane computes 2 output columns.
__global__ void k_spmm2g2(const float* __restrict__ W2,
                          const float* __restrict__ b2,
                          float* __restrict__ out, int n, int ecount) {
    __shared__ float sW2[HID * NLAB];  // 4 KB
    __shared__ float sb2[NLAB];
    int tid = threadIdx.x;             // 256
    for (int i = tid; i < HID * NLAB; i += 256) sW2[i] = W2[i];
    if (tid < NLAB) sb2[tid] = b2[tid];
    __syncthreads();

    int warp = (blockIdx.x * 256 + tid) >> 5;
    if (warp >= n) return;
    int lane = tid & 31;
    int sub = lane & 3;
    int grp = lane >> 2;
    int v = warp;
    int start = g_row_start[v];
    int end = (v + 1 < n) ? g_row_start[v + 1] : ecount;

    float ax = 0.f, ay = 0.f, az = 0.f, aw = 0.f;
    for (int e = start + grp; e < end; e += 8) {
        int s = __ldg(&g_csr[e]);
        float4 x = *(const float4*)(g_hmid + s * HID + sub * 4);
        ax += x.x; ay += x.y; az += x.z; aw += x.w;
    }
    #pragma unroll
    for (int off = 4; off < 32; off <<= 1) {
        ax += __shfl_xor_sync(0xffffffff, ax, off);
        ay += __shfl_xor_sync(0xffffffff, ay, off);
        az += __shfl_xor_sync(0xffffffff, az, off);
        aw += __shfl_xor_sync(0xffffffff, aw, off);
    }
    // after the xor-reduce, every lane with the same 'sub' holds the sum;
    // broadcast the 16 h2 values (from lanes 0..3) to all lanes.
    float nd = g_norm_dst[v];
    float h[HID];
    #pragma unroll
    for (int j = 0; j < 4; j++) {
        h[4 * j + 0] = __shfl_sync(0xffffffff, ax, j) * nd;
        h[4 * j + 1] = __shfl_sync(0xffffffff, ay, j) * nd;
        h[4 * j + 2] = __shfl_sync(0xffffffff, az, j) * nd;
        h[4 * j + 3] = __shfl_sync(0xffffffff, aw, j) * nd;
    }
    float acc0 = sb2[lane];
    float acc1 = sb2[lane + 32];
    #pragma unroll
    for (int k = 0; k < HID; k++) {
        acc0 += h[k] * sW2[k * NLAB + lane];
        acc1 += h[k] * sW2[k * NLAB + lane + 32];
    }
    out[v * NLAB + lane]      = acc0;
    out[v * NLAB + lane + 32] = acc1;
}

// ---------------- launch ----------------
extern "C" void kernel_launch(void* const* d_in, const int* in_sizes, int n_in,
                              void* d_out, int out_size) {
    int n = out_size / NLAB;
    if (n > NMAX) n = NMAX;

    // Identify inputs by element-count signature (robust to metadata order).
    int idx_X = -1, idx_W1 = -1, idx_b1 = -1, idx_W2 = -1, idx_b2 = -1;
    int idx_e1 = -1, idx_e2 = -1;
    for (int i = 0; i < n_in; i++) {
        int sz = in_sizes[i];
        if (sz == n * F_IN)            idx_X = i;
        else if (sz == F_IN * HID)     idx_W1 = i;
        else if (sz == HID)            idx_b1 = i;
        else if (sz == HID * NLAB)     idx_W2 = i;
        else if (sz == NLAB)           idx_b2 = i;
        else if (idx_e1 < 0)           idx_e1 = i;
        else                           idx_e2 = i;
    }

    // src/dst by ordering convention (see round-3 notes).
    int idx_src, idx_dst;
    if (idx_e1 > idx_X) { idx_src = idx_e1; idx_dst = idx_e2; }
    else                { idx_dst = idx_e1; idx_src = idx_e2; }

    const float* X   = (const float*)d_in[idx_X];
    const float* W1  = (const float*)d_in[idx_W1];
    const float* b1  = (const float*)d_in[idx_b1];
    const float* W2  = (const float*)d_in[idx_W2];
    const float* b2  = (const float*)d_in[idx_b2];
    const void*  esrc = d_in[idx_src];
    const void*  edst = d_in[idx_dst];

    int ecount = in_sizes[idx_src];
    if (ecount > EMAX) ecount = EMAX;

    int gb256_n = (n + 255) / 256;
    int gb256_e = (ecount + 255) / 256;
    int nblocks_scan = (n + 1023) / 1024;

    k_init<<<gb256_n, 256>>>(esrc, ecount, n);
    k_convdeg<<<gb256_e, 256>>>(esrc, edst, ecount, n);
    k_scan1<<<nblocks_scan, 1024>>>(n);
    k_scan3<<<gb256_n, 256>>>(n);
    k_csr_fill<<<gb256_e, 256>>>(ecount);

    k_gemm1<<<(n + 511) / 512, 256>>>(X, W1, n);

    int spmm_blocks = (n * 32 + 255) / 256;
    k_spmm1<<<spmm_blocks, 256>>>(b1, n, ecount);
    k_spmm2g2<<<spmm_blocks, 256>>>(W2, b2, (float*)d_out, n, ecount);
}

// round 8
// speedup vs baseline: 1.4333x; 1.1092x over previous
#include <cuda_runtime.h>
#include <math.h>

#define NMAX 100000
#define EMAX 3200000
#define F_IN 512
#define HID 16
#define NLAB 64

// ---------------- device scratch (no allocations allowed) ----------------
// ONLY referenced inside device code (GB300 ATS silently accepts host-shadow
// addresses — never pass these as kernel args).
__device__ float g_norm_src[NMAX];
__device__ float g_norm_dst[NMAX];
__device__ int   g_deg_out[NMAX];
__device__ int   g_deg_in[NMAX];
__device__ int   g_row_start[NMAX];
__device__ int   g_bsum[128];
__device__ int   g_csr[EMAX];
__device__ int   g_esrc[EMAX];
__device__ int   g_edst[EMAX];
__device__ int   g_slot[EMAX];        // within-dst-node slot of each edge
__device__ int   g_fmt;               // 0=int64, 1=int32, 2=float32, 3=float64
__device__ float g_hpre[NMAX * HID];  // X @ W1 (unscaled, then *= norm_src)
__device__ float g_hmid[NMAX * HID];  // relu(spmm*nd + b1) * norm_src

// ---------------- f32x2 packed-FMA helpers ----------------
__device__ __forceinline__ unsigned long long pack2(float v) {
    unsigned long long r;
    asm("mov.b64 %0, {%1, %1};" : "=l"(r) : "f"(v));
    return r;
}
__device__ __forceinline__ void fma2(unsigned long long& acc,
                                     unsigned long long a,
                                     unsigned long long b) {
    asm("fma.rn.f32x2 %0, %1, %2, %0;" : "+l"(acc) : "l"(a), "l"(b));
}
__device__ __forceinline__ float2 unpack2(unsigned long long v) {
    float2 r;
    asm("mov.b64 {%0, %1}, %2;" : "=f"(r.x), "=f"(r.y) : "l"(v));
    return r;
}

// ---------------- init: zero degrees + edge-dtype probe ----------------
__global__ void k_init(const void* __restrict__ src, int ecount, int n) {
    int i = blockIdx.x * blockDim.x + threadIdx.x;
    if (i < n) { g_deg_out[i] = 0; g_deg_in[i] = 0; }
    if (blockIdx.x == 0) {
        __shared__ int ok64, ok32, okf32, okf64;
        if (threadIdx.x == 0) { ok64 = 1; ok32 = 1; okf32 = 1; okf64 = 1; }
        __syncthreads();
        int nprobe = ecount < 1024 ? ecount : 1024;
        for (int e = threadIdx.x; e < nprobe; e += blockDim.x) {
            long long v64 = ((const long long*)src)[e];
            if (v64 < 0 || v64 >= (long long)n) atomicAnd(&ok64, 0);
            int v32 = ((const int*)src)[e];
            if (v32 < 0 || v32 >= n) atomicAnd(&ok32, 0);
            float f = ((const float*)src)[e];
            if (!(f >= 0.f && f < (float)n && f == floorf(f))) atomicAnd(&okf32, 0);
            double d = ((const double*)src)[e];
            if (!(d >= 0.0 && d < (double)n && d == floor(d))) atomicAnd(&okf64, 0);
        }
        __syncthreads();
        if (threadIdx.x == 0)
            g_fmt = ok64 ? 0 : (ok32 ? 1 : (okf32 ? 2 : (okf64 ? 3 : 1)));
    }
}

// ---------------- device parts ----------------

// convert + degree count + slot assignment (one edge per thread)
__device__ __forceinline__ void convdeg_part(const void* __restrict__ src,
                                             const void* __restrict__ dst,
                                             int e, int ecount, int n) {
    if (e >= ecount) return;
    int fmt = g_fmt;
    int s, d;
    if (fmt == 0) {
        s = (int)__ldcs((const long long*)src + e);
        d = (int)__ldcs((const long long*)dst + e);
    } else if (fmt == 1) {
        s = __ldcs((const int*)src + e);
        d = __ldcs((const int*)dst + e);
    } else if (fmt == 2) {
        s = (int)__ldcs((const float*)src + e);
        d = (int)__ldcs((const float*)dst + e);
    } else {
        s = (int)__ldcs((const double*)src + e);
        d = (int)__ldcs((const double*)dst + e);
    }
    s = s < 0 ? 0 : (s >= n ? n - 1 : s);
    d = d < 0 ? 0 : (d >= n ? n - 1 : d);
    g_esrc[e] = s;
    g_edst[e] = d;
    atomicAdd(&g_deg_out[s], 1);
    g_slot[e] = atomicAdd(&g_deg_in[d], 1);   // slot doubles as degree count
}

// GEMM1 (UNSCALED): g_hpre[row] = X[row] @ W1.  2 rows/thread, f32x2 FMA.
__device__ __forceinline__ void gemm1_part(const float* __restrict__ X,
                                           const float* __restrict__ W1,
                                           float* __restrict__ sW1,
                                           int gblk, int n) {
    int tid = threadIdx.x;  // 256
    #pragma unroll
    for (int i = tid; i < (F_IN * HID) / 4; i += 256)
        ((float4*)sW1)[i] = ((const float4*)W1)[i];
    __syncthreads();

    int row0 = gblk * 512 + tid;
    int row1 = row0 + 256;
    if (row0 >= n) return;
    bool has1 = (row1 < n);
    int row1c = has1 ? row1 : row0;

    unsigned long long acc0[8], acc1[8];
    #pragma unroll
    for (int p = 0; p < 8; p++) { acc0[p] = 0ull; acc1[p] = 0ull; }

    const float4* xb0 = (const float4*)(X + (size_t)row0 * F_IN);
    const float4* xb1 = (const float4*)(X + (size_t)row1c * F_IN);

    for (int c = 0; c < F_IN / 4; c++) {
        float4 x0 = __ldcs(xb0 + c);
        float4 x1 = __ldcs(xb1 + c);
        const float xs0[4] = {x0.x, x0.y, x0.z, x0.w};
        const float xs1[4] = {x1.x, x1.y, x1.z, x1.w};
        #pragma unroll
        for (int k = 0; k < 4; k++) {
            unsigned long long xp0 = pack2(xs0[k]);
            unsigned long long xp1 = pack2(xs1[k]);
            const unsigned long long* w =
                (const unsigned long long*)&sW1[(4 * c + k) * HID];
            #pragma unroll
            for (int p = 0; p < 8; p++) {
                unsigned long long wp = w[p];
                fma2(acc0[p], xp0, wp);
                fma2(acc1[p], xp1, wp);
            }
        }
    }

    float* o0 = g_hpre + row0 * HID;
    #pragma unroll
    for (int p = 0; p < 8; p += 2) {
        float2 a = unpack2(acc0[p]);
        float2 b = unpack2(acc0[p + 1]);
        *(float4*)(o0 + 2 * p) = make_float4(a.x, a.y, b.x, b.y);
    }
    if (has1) {
        float* o1 = g_hpre + row1 * HID;
        #pragma unroll
        for (int p = 0; p < 8; p += 2) {
            float2 a = unpack2(acc1[p]);
            float2 b = unpack2(acc1[p + 1]);
            *(float4*)(o1 + 2 * p) = make_float4(a.x, a.y, b.x, b.y);
        }
    }
}

// ---------------- fused kernel 1: gemm1 (blocks first) || convdeg ----------------
__global__ void __launch_bounds__(256)
k_fused1(const float* __restrict__ X, const float* __restrict__ W1,
         const void* __restrict__ src, const void* __restrict__ dst,
         int ecount, int n, int gemm_blocks) {
    __shared__ float sW1[F_IN * HID];  // used only by gemm role (32 KB)
    if ((int)blockIdx.x < gemm_blocks) {
        gemm1_part(X, W1, sW1, blockIdx.x, n);
    } else {
        int e = (blockIdx.x - gemm_blocks) * 256 + threadIdx.x;
        convdeg_part(src, dst, e, ecount, n);
    }
}

// ---------------- scan over deg_in (block-level, shuffle) ----------------
__global__ void k_scan1(int n) {
    __shared__ int wsum[32];
    int tid = threadIdx.x;
    int i = blockIdx.x * 1024 + tid;
    int lane = tid & 31, wid = tid >> 5;
    int v = (i < n) ? g_deg_in[i] : 0;
    int s = v;
    #pragma unroll
    for (int off = 1; off < 32; off <<= 1) {
        int t = __shfl_up_sync(0xffffffff, s, off);
        if (lane >= off) s += t;
    }
    if (lane == 31) wsum[wid] = s;
    __syncthreads();
    if (wid == 0) {
        int w = wsum[lane];
        #pragma unroll
        for (int off = 1; off < 32; off <<= 1) {
            int t = __shfl_up_sync(0xffffffff, w, off);
            if (lane >= off) w += t;
        }
        wsum[lane] = w;
    }
    __syncthreads();
    int base = (wid > 0) ? wsum[wid - 1] : 0;
    int incl = s + base;
    if (i < n) g_row_start[i] = incl - v;
    if (tid == 1023) g_bsum[blockIdx.x] = incl;
}

// finalize row_start + norms (no fill array needed anymore)
__global__ void k_scan3(int n) {
    __shared__ int base_s;
    int nb1 = blockIdx.x >> 2;
    if (threadIdx.x < 32) {
        int lane = threadIdx.x;
        int acc = 0;
        for (int b = lane; b < nb1; b += 32) acc += g_bsum[b];
        #pragma unroll
        for (int off = 16; off; off >>= 1)
            acc += __shfl_xor_sync(0xffffffff, acc, off);
        if (lane == 0) base_s = acc;
    }
    __syncthreads();
    int i = blockIdx.x * 256 + threadIdx.x;
    if (i >= n) return;
    g_row_start[i] += base_s;
    int dout = g_deg_out[i]; if (dout < 1) dout = 1;
    int din  = g_deg_in[i];  if (din  < 1) din  = 1;
    g_norm_src[i] = rsqrtf((float)dout);
    g_norm_dst[i] = rsqrtf((float)din);
}

// ---------------- fused kernel 2: csr fill (no atomics) || hpre scaling ----------------
__global__ void __launch_bounds__(256)
k_fused2(int ecount, int n, int csr_blocks) {
    if ((int)blockIdx.x < csr_blocks) {
        int e = blockIdx.x * 256 + threadIdx.x;
        if (e < ecount) {
            int d = __ldcs(&g_edst[e]);
            int s = __ldcs(&g_esrc[e]);
            int sl = __ldcs(&g_slot[e]);
            g_csr[g_row_start[d] + sl] = s;
        }
    } else {
        int i = (blockIdx.x - csr_blocks) * 256 + threadIdx.x;  // float4 index
        if (i < n * (HID / 4)) {
            float ns = g_norm_src[i >> 2];
            float4* p = (float4*)g_hpre + i;
            float4 v = *p;
            v.x *= ns; v.y *= ns; v.z *= ns; v.w *= ns;
            *p = v;
        }
    }
}

// ---------------- SpMM stage 1: g_hmid = relu(spmm(g_hpre)*nd + b1)*ns ----------------
__global__ void k_spmm1(const float* __restrict__ b1, int n, int ecount) {
    int warp = (blockIdx.x * blockDim.x + threadIdx.x) >> 5;
    if (warp >= n) return;
    int lane = threadIdx.x & 31;
    int sub = lane & 3;
    int grp = lane >> 2;
    int v = warp;
    int start = g_row_start[v];
    int end = (v + 1 < n) ? g_row_start[v + 1] : ecount;

    float ax = 0.f, ay = 0.f, az = 0.f, aw = 0.f;
    for (int e = start + grp; e < end; e += 8) {
        int s = __ldg(&g_csr[e]);
        float4 x = *(const float4*)(g_hpre + s * HID + sub * 4);
        ax += x.x; ay += x.y; az += x.z; aw += x.w;
    }
    #pragma unroll
    for (int off = 4; off < 32; off <<= 1) {
        ax += __shfl_xor_sync(0xffffffff, ax, off);
        ay += __shfl_xor_sync(0xffffffff, ay, off);
        az += __shfl_xor_sync(0xffffffff, az, off);
        aw += __shfl_xor_sync(0xffffffff, aw, off);
    }
    if (lane < 4) {
        float nd = g_norm_dst[v];
        float ns = g_norm_src[v];
        float4 bb = ((const float4*)b1)[lane];
        float4 r;
        r.x = fmaxf(ax * nd + bb.x, 0.f) * ns;
        r.y = fmaxf(ay * nd + bb.y, 0.f) * ns;
        r.z = fmaxf(az * nd + bb.z, 0.f) * ns;
        r.w = fmaxf(aw * nd + bb.w, 0.f) * ns;
        *(float4*)(g_hmid + v * HID + lane * 4) = r;
    }
}

// ---------------- SpMM stage 2 + GEMM2 fused ----------------
__global__ void k_spmm2g2(const float* __restrict__ W2,
                          const float* __restrict__ b2,
                          float* __restrict__ out, int n, int ecount) {
    __shared__ float sW2[HID * NLAB];
    __shared__ float sb2[NLAB];
    int tid = threadIdx.x;  // 256
    for (int i = tid; i < HID * NLAB; i += 256) sW2[i] = W2[i];
    if (tid < NLAB) sb2[tid] = b2[tid];
    __syncthreads();

    int warp = (blockIdx.x * 256 + tid) >> 5;
    if (warp >= n) return;
    int lane = tid & 31;
    int sub = lane & 3;
    int grp = lane >> 2;
    int v = warp;
    int start = g_row_start[v];
    int end = (v + 1 < n) ? g_row_start[v + 1] : ecount;

    float ax = 0.f, ay = 0.f, az = 0.f, aw = 0.f;
    for (int e = start + grp; e < end; e += 8) {
        int s = __ldg(&g_csr[e]);
        float4 x = *(const float4*)(g_hmid + s * HID + sub * 4);
        ax += x.x; ay += x.y; az += x.z; aw += x.w;
    }
    #pragma unroll
    for (int off = 4; off < 32; off <<= 1) {
        ax += __shfl_xor_sync(0xffffffff, ax, off);
        ay += __shfl_xor_sync(0xffffffff, ay, off);
        az += __shfl_xor_sync(0xffffffff, az, off);
        aw += __shfl_xor_sync(0xffffffff, aw, off);
    }
    float nd = g_norm_dst[v];
    float h[HID];
    #pragma unroll
    for (int j = 0; j < 4; j++) {
        h[4 * j + 0] = __shfl_sync(0xffffffff, ax, j) * nd;
        h[4 * j + 1] = __shfl_sync(0xffffffff, ay, j) * nd;
        h[4 * j + 2] = __shfl_sync(0xffffffff, az, j) * nd;
        h[4 * j + 3] = __shfl_sync(0xffffffff, aw, j) * nd;
    }
    float acc0 = sb2[lane];
    float acc1 = sb2[lane + 32];
    #pragma unroll
    for (int k = 0; k < HID; k++) {
        acc0 += h[k] * sW2[k * NLAB + lane];
        acc1 += h[k] * sW2[k * NLAB + lane + 32];
    }
    out[v * NLAB + lane]      = acc0;
    out[v * NLAB + lane + 32] = acc1;
}

// ---------------- launch ----------------
extern "C" void kernel_launch(void* const* d_in, const int* in_sizes, int n_in,
                              void* d_out, int out_size) {
    int n = out_size / NLAB;
    if (n > NMAX) n = NMAX;

    // Identify inputs by element-count signature (robust to metadata order).
    int idx_X = -1, idx_W1 = -1, idx_b1 = -1, idx_W2 = -1, idx_b2 = -1;
    int idx_e1 = -1, idx_e2 = -1;
    for (int i = 0; i < n_in; i++) {
        int sz = in_sizes[i];
        if (sz == n * F_IN)            idx_X = i;
        else if (sz == F_IN * HID)     idx_W1 = i;
        else if (sz == HID)            idx_b1 = i;
        else if (sz == HID * NLAB)     idx_W2 = i;
        else if (sz == NLAB)           idx_b2 = i;
        else if (idx_e1 < 0)           idx_e1 = i;
        else                           idx_e2 = i;
    }

    // src/dst by ordering convention (see round-3 notes).
    int idx_src, idx_dst;
    if (idx_e1 > idx_X) { idx_src = idx_e1; idx_dst = idx_e2; }
    else                { idx_dst = idx_e1; idx_src = idx_e2; }

    const float* X   = (const float*)d_in[idx_X];
    const float* W1  = (const float*)d_in[idx_W1];
    const float* b1  = (const float*)d_in[idx_b1];
    const float* W2  = (const float*)d_in[idx_W2];
    const float* b2  = (const float*)d_in[idx_b2];
    const void*  esrc = d_in[idx_src];
    const void*  edst = d_in[idx_dst];

    int ecount = in_sizes[idx_src];
    if (ecount > EMAX) ecount = EMAX;

    int gb256_n = (n + 255) / 256;
    int gb256_e = (ecount + 255) / 256;
    int nblocks_scan = (n + 1023) / 1024;
    int gemm_blocks = (n + 511) / 512;
    int scale_blocks = (n * (HID / 4) + 255) / 256;

    k_init<<<gb256_n, 256>>>(esrc, ecount, n);
    k_fused1<<<gemm_blocks + gb256_e, 256>>>(X, W1, esrc, edst,
                                             ecount, n, gemm_blocks);
    k_scan1<<<nblocks_scan, 1024>>>(n);
    k_scan3<<<gb256_n, 256>>>(n);
    k_fused2<<<gb256_e + scale_blocks, 256>>>(ecount, n, gb256_e);

    int spmm_blocks = (n * 32 + 255) / 256;
    k_spmm1<<<spmm_blocks, 256>>>(b1, n, ecount);
    k_spmm2g2<<<spmm_blocks, 256>>>(W2, b2, (float*)d_out, n, ecount);
}